// round 2
// baseline (speedup 1.0000x reference)
#include <cuda_runtime.h>

#define H 256
#define D 8
#define BN_EPS 1e-5f

// ---------------- device scratch (static, allocation-free) ----------------
__device__ float g_P [H * D];   // Wo @ Wp
__device__ float g_T2[H * D];   // Wv @ P
__device__ float g_M [H * D];   // W2 @ T2
__device__ float g_c [D];       // folded bias chain
__device__ float g_sum  [H];    // per-column sum of h
__device__ float g_sumsq[H];    // per-column sum of h^2
__device__ float g_Ms[H * D];   // diag(s) @ M
__device__ float g_c8[D];       // t @ M + c

// ---------------- fold kernels (tiny) ----------------
// P = Wo @ Wp  ; also zero the stat accumulators (graph-replay safe)
__global__ void k_fold1(const float* __restrict__ Wo, const float* __restrict__ Wp) {
    int t = blockIdx.x * blockDim.x + threadIdx.x;   // 0..2047
    int i = t >> 3, d = t & 7;
    float acc = 0.f;
#pragma unroll 8
    for (int k = 0; k < H; k++) acc = fmaf(Wo[i * H + k], Wp[k * D + d], acc);
    g_P[i * D + d] = acc;
    if (t < H) { g_sum[t] = 0.f; g_sumsq[t] = 0.f; }
}

// T2 = Wv @ P
__global__ void k_fold2(const float* __restrict__ Wv) {
    int t = blockIdx.x * blockDim.x + threadIdx.x;
    int i = t >> 3, d = t & 7;
    float acc = 0.f;
#pragma unroll 8
    for (int k = 0; k < H; k++) acc = fmaf(Wv[i * H + k], g_P[k * D + d], acc);
    g_T2[i * D + d] = acc;
}

// M = W2 @ T2 ; c = b2@T2 + bv@P + bo@Wp + bp
__global__ void k_fold3(const float* __restrict__ W2, const float* __restrict__ b2,
                        const float* __restrict__ bv, const float* __restrict__ bo,
                        const float* __restrict__ bp, const float* __restrict__ Wp) {
    int t = blockIdx.x * blockDim.x + threadIdx.x;
    int i = t >> 3, d = t & 7;
    float acc = 0.f;
#pragma unroll 8
    for (int k = 0; k < H; k++) acc = fmaf(W2[i * H + k], g_T2[k * D + d], acc);
    g_M[i * D + d] = acc;
    if (t < D) {
        float c = bp[t];
        for (int k = 0; k < H; k++) {
            c = fmaf(b2[k], g_T2[k * D + t], c);
            c = fmaf(bv[k], g_P [k * D + t], c);
            c = fmaf(bo[k], Wp  [k * D + t], c);
        }
        g_c[t] = c;
    }
}

// ---------------- pass 1: batch statistics of h = relu(nc@W1 + b1) ----------------
// column-owner layout: thread t owns column t; block stages 256 edges' nc in smem.
__global__ void __launch_bounds__(256) k_pass1(
    const float* __restrict__ nf, const int* __restrict__ ei,
    const float* __restrict__ W1, const float* __restrict__ b1, int E) {
    __shared__ float4 ncs[256 * 2];          // [edge][2 x float4]
    const int t = threadIdx.x;

    float w[8];
#pragma unroll
    for (int k = 0; k < 8; k++) w[k] = W1[k * H + t];   // coalesced
    const float bb = b1[t];

    // two independent accumulator chains (break fma RAW chain, reduce rounding)
    float sumA = 0.f, ssqA = 0.f;
    float sumB = 0.f, ssqB = 0.f;
    const int numTiles = (E + 255) >> 8;

    for (int tile = blockIdx.x; tile < numTiles; tile += gridDim.x) {
        const int base = tile << 8;
        const int cnt  = min(256, E - base);
        __syncthreads();                      // protect ncs from prior readers
        if (t < cnt) {
            const int e  = base + t;
            const int s0 = ei[e];
            const int s1 = ei[E + e];
            const float4* a = (const float4*)(nf + (size_t)s0 * D);
            const float4* b = (const float4*)(nf + (size_t)s1 * D);
            float4 x0 = a[0], x1 = a[1], y0 = b[0], y1 = b[1];
            float4 n0, n1;
            n0.x = 0.5f * (x0.x + y0.x); n0.y = 0.5f * (x0.y + y0.y);
            n0.z = 0.5f * (x0.z + y0.z); n0.w = 0.5f * (x0.w + y0.w);
            n1.x = 0.5f * (x1.x + y1.x); n1.y = 0.5f * (x1.y + y1.y);
            n1.z = 0.5f * (x1.z + y1.z); n1.w = 0.5f * (x1.w + y1.w);
            ncs[t * 2 + 0] = n0;
            ncs[t * 2 + 1] = n1;
        }
        __syncthreads();
        int e = 0;
#pragma unroll 2
        for (; e + 1 < cnt; e += 2) {
            float4 a0 = ncs[e * 2 + 0];
            float4 b0 = ncs[e * 2 + 1];
            float4 a1 = ncs[e * 2 + 2];
            float4 b1v = ncs[e * 2 + 3];
            float q0 = bb, q1 = bb;
            q0 = fmaf(a0.x, w[0], q0); q1 = fmaf(a1.x, w[0], q1);
            q0 = fmaf(a0.y, w[1], q0); q1 = fmaf(a1.y, w[1], q1);
            q0 = fmaf(a0.z, w[2], q0); q1 = fmaf(a1.z, w[2], q1);
            q0 = fmaf(a0.w, w[3], q0); q1 = fmaf(a1.w, w[3], q1);
            q0 = fmaf(b0.x, w[4], q0); q1 = fmaf(b1v.x, w[4], q1);
            q0 = fmaf(b0.y, w[5], q0); q1 = fmaf(b1v.y, w[5], q1);
            q0 = fmaf(b0.z, w[6], q0); q1 = fmaf(b1v.z, w[6], q1);
            q0 = fmaf(b0.w, w[7], q0); q1 = fmaf(b1v.w, w[7], q1);
            float h0 = fmaxf(q0, 0.f);
            float h1 = fmaxf(q1, 0.f);
            sumA += h0;                sumB += h1;
            ssqA = fmaf(h0, h0, ssqA); ssqB = fmaf(h1, h1, ssqB);
        }
        if (e < cnt) {
            float4 a0 = ncs[e * 2 + 0];
            float4 b0 = ncs[e * 2 + 1];
            float q0 = bb;
            q0 = fmaf(a0.x, w[0], q0); q0 = fmaf(a0.y, w[1], q0);
            q0 = fmaf(a0.z, w[2], q0); q0 = fmaf(a0.w, w[3], q0);
            q0 = fmaf(b0.x, w[4], q0); q0 = fmaf(b0.y, w[5], q0);
            q0 = fmaf(b0.z, w[6], q0); q0 = fmaf(b0.w, w[7], q0);
            float h0 = fmaxf(q0, 0.f);
            sumA += h0;
            ssqA = fmaf(h0, h0, ssqA);
        }
    }
    atomicAdd(&g_sum[t],   sumA + sumB);
    atomicAdd(&g_sumsq[t], ssqA + ssqB);
}

// ---------------- finalize: fold BN affine into M -> Ms, c8 ----------------
__global__ void k_finalize(const float* __restrict__ gamma,
                           const float* __restrict__ beta, float invE) {
    __shared__ float tvs[H];
    const int j = threadIdx.x;
    float mu  = g_sum[j] * invE;
    float var = fmaf(-mu, mu, g_sumsq[j] * invE);   // biased var
    float s   = gamma[j] * rsqrtf(var + BN_EPS);
    float tv  = fmaf(-mu, s, beta[j]);
#pragma unroll
    for (int d = 0; d < D; d++) g_Ms[j * D + d] = s * g_M[j * D + d];
    tvs[j] = tv;
    __syncthreads();
    if (j < D) {
        float acc = g_c[j];
        for (int k = 0; k < H; k++) acc = fmaf(tvs[k], g_M[k * D + j], acc);
        g_c8[j] = acc;
    }
}

// ---------------- pass 2: out = edge_attr + 0.5*(relu(nc@W1+b1) @ Ms + c8) ----------------
// edge-owner layout: one thread per edge; W1^T, b1, Ms, c8 broadcast from smem.
__global__ void __launch_bounds__(256) k_pass2(
    const float* __restrict__ ea, const float* __restrict__ nf,
    const int* __restrict__ ei,
    const float* __restrict__ W1, const float* __restrict__ b1,
    float* __restrict__ out, int E) {
    __shared__ float4 w1t[H * 2];    // [j][k0..3],[k4..7]  (W1 transposed)
    __shared__ float4 msS[H * 2];    // [j][d0..3],[d4..7]
    __shared__ float  b1s[H];
    __shared__ float  c8s[D];

    const int t = threadIdx.x;
    float* w1f = (float*)w1t;
    float* msf = (float*)msS;
    for (int idx = t; idx < H * D; idx += 256) {
        int j = idx >> 3, k = idx & 7;
        w1f[j * 8 + k] = W1[k * H + j];
        msf[idx]       = g_Ms[idx];
    }
    b1s[t] = b1[t];
    if (t < D) c8s[t] = g_c8[t];
    __syncthreads();

    const int e = blockIdx.x * 256 + t;
    if (e >= E) return;

    const int s0 = ei[e];
    const int s1 = ei[E + e];
    const float4* a = (const float4*)(nf + (size_t)s0 * D);
    const float4* b = (const float4*)(nf + (size_t)s1 * D);
    float4 x0 = a[0], x1 = a[1], y0 = b[0], y1 = b[1];
    const float n0 = 0.5f * (x0.x + y0.x), n1 = 0.5f * (x0.y + y0.y);
    const float n2 = 0.5f * (x0.z + y0.z), n3 = 0.5f * (x0.w + y0.w);
    const float n4 = 0.5f * (x1.x + y1.x), n5 = 0.5f * (x1.y + y1.y);
    const float n6 = 0.5f * (x1.z + y1.z), n7 = 0.5f * (x1.w + y1.w);

    float acc0 = 0.f, acc1 = 0.f, acc2 = 0.f, acc3 = 0.f;
    float acc4 = 0.f, acc5 = 0.f, acc6 = 0.f, acc7 = 0.f;

#pragma unroll 4
    for (int j = 0; j < H; j++) {
        float4 wa = w1t[j * 2 + 0];
        float4 wb = w1t[j * 2 + 1];
        float q = b1s[j];
        q = fmaf(n0, wa.x, q); q = fmaf(n1, wa.y, q);
        q = fmaf(n2, wa.z, q); q = fmaf(n3, wa.w, q);
        q = fmaf(n4, wb.x, q); q = fmaf(n5, wb.y, q);
        q = fmaf(n6, wb.z, q); q = fmaf(n7, wb.w, q);
        float h = fmaxf(q, 0.f);
        float4 ma = msS[j * 2 + 0];
        float4 mb = msS[j * 2 + 1];
        acc0 = fmaf(h, ma.x, acc0); acc1 = fmaf(h, ma.y, acc1);
        acc2 = fmaf(h, ma.z, acc2); acc3 = fmaf(h, ma.w, acc3);
        acc4 = fmaf(h, mb.x, acc4); acc5 = fmaf(h, mb.y, acc5);
        acc6 = fmaf(h, mb.z, acc6); acc7 = fmaf(h, mb.w, acc7);
    }

    const float4* eap = (const float4*)(ea + (size_t)e * D);
    float4 e0 = eap[0], e1 = eap[1];
    float4 o0, o1;
    o0.x = e0.x + 0.5f * (acc0 + c8s[0]);
    o0.y = e0.y + 0.5f * (acc1 + c8s[1]);
    o0.z = e0.z + 0.5f * (acc2 + c8s[2]);
    o0.w = e0.w + 0.5f * (acc3 + c8s[3]);
    o1.x = e1.x + 0.5f * (acc4 + c8s[4]);
    o1.y = e1.y + 0.5f * (acc5 + c8s[5]);
    o1.z = e1.z + 0.5f * (acc6 + c8s[6]);
    o1.w = e1.w + 0.5f * (acc7 + c8s[7]);
    float4* op = (float4*)(out + (size_t)e * D);
    op[0] = o0;
    op[1] = o1;
}

// ---------------- launcher ----------------
extern "C" void kernel_launch(void* const* d_in, const int* in_sizes, int n_in,
                              void* d_out, int out_size) {
    const float* edge_attr     = (const float*)d_in[0];
    const float* node_features = (const float*)d_in[1];
    const int*   edge_index    = (const int*)  d_in[2];
    // d_in[3..8]: edge-encoder params — provably unused by the reference output
    const float* n_W1    = (const float*)d_in[9];
    const float* n_b1    = (const float*)d_in[10];
    const float* n_gamma = (const float*)d_in[11];
    const float* n_beta  = (const float*)d_in[12];
    const float* n_W2    = (const float*)d_in[13];
    const float* n_b2    = (const float*)d_in[14];
    const float* Wv      = (const float*)d_in[15];
    const float* bv      = (const float*)d_in[16];
    const float* Wo      = (const float*)d_in[17];
    const float* bo      = (const float*)d_in[18];
    const float* Wp      = (const float*)d_in[19];
    const float* bp      = (const float*)d_in[20];

    const int E = in_sizes[0] / D;
    float* out = (float*)d_out;

    k_fold1<<<16, 128>>>(Wo, Wp);
    k_fold2<<<16, 128>>>(Wv);
    k_fold3<<<16, 128>>>(n_W2, n_b2, bv, bo, bp, Wp);
    k_pass1<<<1184, 256>>>(node_features, edge_index, n_W1, n_b1, E);
    k_finalize<<<1, 256>>>(n_gamma, n_beta, 1.0f / (float)E);
    k_pass2<<<(E + 255) / 256, 256>>>(edge_attr, node_features, edge_index,
                                      n_W1, n_b1, out, E);
}

// round 3
// speedup vs baseline: 1.1656x; 1.1656x over previous
#include <cuda_runtime.h>

#define H 256
#define D 8
#define BN_EPS 1e-5f

typedef unsigned long long u64;

// ---------------- packed f32x2 helpers ----------------
__device__ __forceinline__ u64 ffma2(u64 a, u64 b, u64 c) {
    u64 d; asm("fma.rn.f32x2 %0, %1, %2, %3;" : "=l"(d) : "l"(a), "l"(b), "l"(c)); return d;
}
__device__ __forceinline__ u64 fadd2(u64 a, u64 b) {
    u64 d; asm("add.rn.f32x2 %0, %1, %2;" : "=l"(d) : "l"(a), "l"(b)); return d;
}
__device__ __forceinline__ u64 pack2(float lo, float hi) {
    u64 d; asm("mov.b64 %0, {%1, %2};" : "=l"(d) : "f"(lo), "f"(hi)); return d;
}
__device__ __forceinline__ float2 unpack2(u64 v) {
    float lo, hi; asm("mov.b64 {%0, %1}, %2;" : "=f"(lo), "=f"(hi) : "l"(v));
    return make_float2(lo, hi);
}
__device__ __forceinline__ u64 abs2(u64 v) {
    u64 d; asm("and.b64 %0, %1, 0x7FFFFFFF7FFFFFFF;" : "=l"(d) : "l"(v)); return d;
}
// relu2: returns 2*relu per lane (q + |q|)
__device__ __forceinline__ u64 relu2x(u64 q) { return fadd2(q, abs2(q)); }

// ---------------- device scratch (static, allocation-free) ----------------
__device__ float g_P [H * D];   // Wo @ Wp
__device__ float g_T2[H * D];   // Wv @ P
__device__ float g_M [H * D];   // W2 @ T2
__device__ float g_c [D];       // folded bias chain
__device__ float g_sum  [H];    // per-column sum of r = 2h
__device__ float g_sumsq[H];    // per-column sum of r^2 = 4h^2
__device__ float g_Ms[H * D];   // 0.25 * diag(s) @ M
__device__ float g_c8[D];       // 0.5 * (t @ M + c)

// ---------------- fold kernels (tiny) ----------------
__global__ void k_fold1(const float* __restrict__ Wo, const float* __restrict__ Wp) {
    int t = blockIdx.x * blockDim.x + threadIdx.x;   // 0..2047
    int i = t >> 3, d = t & 7;
    float acc = 0.f;
#pragma unroll 8
    for (int k = 0; k < H; k++) acc = fmaf(Wo[i * H + k], Wp[k * D + d], acc);
    g_P[i * D + d] = acc;
    if (t < H) { g_sum[t] = 0.f; g_sumsq[t] = 0.f; }
}

__global__ void k_fold2(const float* __restrict__ Wv) {
    int t = blockIdx.x * blockDim.x + threadIdx.x;
    int i = t >> 3, d = t & 7;
    float acc = 0.f;
#pragma unroll 8
    for (int k = 0; k < H; k++) acc = fmaf(Wv[i * H + k], g_P[k * D + d], acc);
    g_T2[i * D + d] = acc;
}

__global__ void k_fold3(const float* __restrict__ W2, const float* __restrict__ b2,
                        const float* __restrict__ bv, const float* __restrict__ bo,
                        const float* __restrict__ bp, const float* __restrict__ Wp) {
    int t = blockIdx.x * blockDim.x + threadIdx.x;
    int i = t >> 3, d = t & 7;
    float acc = 0.f;
#pragma unroll 8
    for (int k = 0; k < H; k++) acc = fmaf(W2[i * H + k], g_T2[k * D + d], acc);
    g_M[i * D + d] = acc;
    if (t < D) {
        float c = bp[t];
        for (int k = 0; k < H; k++) {
            c = fmaf(b2[k], g_T2[k * D + t], c);
            c = fmaf(bv[k], g_P [k * D + t], c);
            c = fmaf(bo[k], Wp  [k * D + t], c);
        }
        g_c[t] = c;
    }
}

// ---------------- pass 1: batch statistics of h = relu(nc@W1 + b1) ----------------
// column-owner; 2 edges packed per f32x2; nc staged TRANSPOSED [k][256].
__global__ void __launch_bounds__(256) k_pass1(
    const float* __restrict__ nf, const int* __restrict__ ei,
    const float* __restrict__ W1, const float* __restrict__ b1, int E) {
    __shared__ float ncsT[8][256];           // [k][edge-in-tile]
    const int t = threadIdx.x;

    u64 w2[8];
#pragma unroll
    for (int k = 0; k < 8; k++) { float w = W1[k * H + t]; w2[k] = pack2(w, w); }
    const float bb = b1[t];
    const u64 b2p = pack2(bb, bb);

    u64 sumA = pack2(0.f, 0.f), ssqA = sumA, sumB = sumA, ssqB = sumA;
    const int numTiles = (E + 255) >> 8;

    for (int tile = blockIdx.x; tile < numTiles; tile += gridDim.x) {
        const int base = tile << 8;
        const int cnt  = min(256, E - base);
        __syncthreads();                      // protect ncsT from prior readers
        if (t < cnt) {
            const int e  = base + t;
            const int s0 = ei[e];
            const int s1 = ei[E + e];
            const float4* a = (const float4*)(nf + (size_t)s0 * D);
            const float4* b = (const float4*)(nf + (size_t)s1 * D);
            float4 x0 = a[0], x1 = a[1], y0 = b[0], y1 = b[1];
            ncsT[0][t] = 0.5f * (x0.x + y0.x);
            ncsT[1][t] = 0.5f * (x0.y + y0.y);
            ncsT[2][t] = 0.5f * (x0.z + y0.z);
            ncsT[3][t] = 0.5f * (x0.w + y0.w);
            ncsT[4][t] = 0.5f * (x1.x + y1.x);
            ncsT[5][t] = 0.5f * (x1.y + y1.y);
            ncsT[6][t] = 0.5f * (x1.z + y1.z);
            ncsT[7][t] = 0.5f * (x1.w + y1.w);
        }
        __syncthreads();
        int e = 0;
        for (; e + 3 < cnt; e += 4) {         // 2 independent packed chains
            u64 q0 = b2p, q1 = b2p;
#pragma unroll
            for (int k = 0; k < 8; k++) {
                u64 n01 = *(const u64*)&ncsT[k][e];
                u64 n23 = *(const u64*)&ncsT[k][e + 2];
                q0 = ffma2(n01, w2[k], q0);
                q1 = ffma2(n23, w2[k], q1);
            }
            u64 r0 = relu2x(q0);
            u64 r1 = relu2x(q1);
            sumA = fadd2(sumA, r0);  sumB = fadd2(sumB, r1);
            ssqA = ffma2(r0, r0, ssqA);  ssqB = ffma2(r1, r1, ssqB);
        }
        for (; e + 1 < cnt; e += 2) {
            u64 q0 = b2p;
#pragma unroll
            for (int k = 0; k < 8; k++)
                q0 = ffma2(*(const u64*)&ncsT[k][e], w2[k], q0);
            u64 r0 = relu2x(q0);
            sumA = fadd2(sumA, r0);
            ssqA = ffma2(r0, r0, ssqA);
        }
        if (e < cnt) {                        // odd tail: hi lane poisoned negative -> r=0
            u64 q0 = pack2(bb, -1e30f);
#pragma unroll
            for (int k = 0; k < 8; k++)
                q0 = ffma2(pack2(ncsT[k][e], 0.f), w2[k], q0);
            u64 r0 = relu2x(q0);
            sumA = fadd2(sumA, r0);
            ssqA = ffma2(r0, r0, ssqA);
        }
    }
    float2 sa = unpack2(fadd2(sumA, sumB));
    float2 qa = unpack2(fadd2(ssqA, ssqB));
    atomicAdd(&g_sum[t],   sa.x + sa.y);      // Σ r  (r = 2h)
    atomicAdd(&g_sumsq[t], qa.x + qa.y);      // Σ r²
}

// ---------------- finalize: fold BN affine (+0.25/0.5 relu factors) into M ----------------
__global__ void k_finalize(const float* __restrict__ gamma,
                           const float* __restrict__ beta, float invE) {
    __shared__ float tvs[H];
    const int j = threadIdx.x;
    float mu  = 0.5f  * g_sum[j]   * invE;              // E[h]
    float eh2 = 0.25f * g_sumsq[j] * invE;              // E[h^2]
    float var = fmaf(-mu, mu, eh2);                     // biased var
    float s   = gamma[j] * rsqrtf(var + BN_EPS);
    float tv  = fmaf(-mu, s, beta[j]);
#pragma unroll
    for (int d = 0; d < D; d++) g_Ms[j * D + d] = 0.25f * s * g_M[j * D + d];
    tvs[j] = tv;
    __syncthreads();
    if (j < D) {
        float acc = g_c[j];
        for (int k = 0; k < H; k++) acc = fmaf(tvs[k], g_M[k * D + j], acc);
        g_c8[j] = 0.5f * acc;
    }
}

// ---------------- pass 2: out = ea + (r @ Ms025) + c8h,  r = 2*relu(nc@W1+b1) ----------------
// edge-owner, 2 edges/thread; columns packed in f32x2 lane pairs.
__global__ void __launch_bounds__(256) k_pass2(
    const float* __restrict__ ea, const float* __restrict__ nf,
    const int* __restrict__ ei,
    const float* __restrict__ W1, const float* __restrict__ b1,
    float* __restrict__ out, int E) {
    __shared__ u64 w2p [128 * 8];   // [jp][k]  = (W1[k][2jp], W1[k][2jp+1])
    __shared__ u64 ms2p[128 * 8];   // [jp][d]  = (Ms[2jp][d], Ms[2jp+1][d])
    __shared__ u64 b2p [128];       // (b1[2jp], b1[2jp+1])
    __shared__ float c8s[D];

    const int t = threadIdx.x;
    for (int idx = t; idx < 128 * 8; idx += 256) {
        int jp = idx >> 3, k = idx & 7;
        w2p [jp * 8 + k] = pack2(W1[k * H + 2 * jp], W1[k * H + 2 * jp + 1]);
        ms2p[jp * 8 + k] = pack2(g_Ms[(2 * jp) * D + k], g_Ms[(2 * jp + 1) * D + k]);
    }
    if (t < 128) b2p[t] = pack2(b1[2 * t], b1[2 * t + 1]);
    if (t < D)   c8s[t] = g_c8[t];
    __syncthreads();

    const int e0r = blockIdx.x * 512 + t;
    const int e1r = e0r + 256;
    const bool v0 = e0r < E, v1 = e1r < E;
    const int e0 = v0 ? e0r : E - 1;
    const int e1 = v1 ? e1r : E - 1;

    // gather + duplicate-pack nc for both edges
    u64 nca[8], ncb[8];
    {
        const int sa0 = ei[e0], sa1 = ei[E + e0];
        const int sb0 = ei[e1], sb1 = ei[E + e1];
        const float4* pa0 = (const float4*)(nf + (size_t)sa0 * D);
        const float4* pa1 = (const float4*)(nf + (size_t)sa1 * D);
        const float4* pb0 = (const float4*)(nf + (size_t)sb0 * D);
        const float4* pb1 = (const float4*)(nf + (size_t)sb1 * D);
        float4 ax0 = pa0[0], ax1 = pa0[1], ay0 = pa1[0], ay1 = pa1[1];
        float4 bx0 = pb0[0], bx1 = pb0[1], by0 = pb1[0], by1 = pb1[1];
        float na[8], nb[8];
        na[0] = 0.5f * (ax0.x + ay0.x); na[1] = 0.5f * (ax0.y + ay0.y);
        na[2] = 0.5f * (ax0.z + ay0.z); na[3] = 0.5f * (ax0.w + ay0.w);
        na[4] = 0.5f * (ax1.x + ay1.x); na[5] = 0.5f * (ax1.y + ay1.y);
        na[6] = 0.5f * (ax1.z + ay1.z); na[7] = 0.5f * (ax1.w + ay1.w);
        nb[0] = 0.5f * (bx0.x + by0.x); nb[1] = 0.5f * (bx0.y + by0.y);
        nb[2] = 0.5f * (bx0.z + by0.z); nb[3] = 0.5f * (bx0.w + by0.w);
        nb[4] = 0.5f * (bx1.x + by1.x); nb[5] = 0.5f * (bx1.y + by1.y);
        nb[6] = 0.5f * (bx1.z + by1.z); nb[7] = 0.5f * (bx1.w + by1.w);
#pragma unroll
        for (int k = 0; k < 8; k++) { nca[k] = pack2(na[k], na[k]); ncb[k] = pack2(nb[k], nb[k]); }
    }

    u64 acca[8], accb[8];
    const u64 z = pack2(0.f, 0.f);
#pragma unroll
    for (int d = 0; d < 8; d++) { acca[d] = z; accb[d] = z; }

#pragma unroll 2
    for (int jp = 0; jp < 128; jp++) {
        const u64* wrow = &w2p[jp * 8];
        u64 qa = b2p[jp], qb = qa;
#pragma unroll
        for (int k = 0; k < 8; k++) {
            u64 w = wrow[k];
            qa = ffma2(nca[k], w, qa);
            qb = ffma2(ncb[k], w, qb);
        }
        u64 ra = relu2x(qa);                  // lanes: columns 2jp, 2jp+1 (×2h)
        u64 rb = relu2x(qb);
        const u64* mrow = &ms2p[jp * 8];
#pragma unroll
        for (int d = 0; d < 8; d++) {
            u64 m = mrow[d];
            acca[d] = ffma2(ra, m, acca[d]);  // lane-wise partial sums over column parity
            accb[d] = ffma2(rb, m, accb[d]);
        }
    }

    if (v0) {
        const float4* eap = (const float4*)(ea + (size_t)e0 * D);
        float4 i0 = eap[0], i1 = eap[1];
        float o[8];
#pragma unroll
        for (int d = 0; d < 8; d++) {
            float2 p = unpack2(acca[d]);
            o[d] = p.x + p.y + c8s[d];
        }
        float4 o0 = make_float4(i0.x + o[0], i0.y + o[1], i0.z + o[2], i0.w + o[3]);
        float4 o1 = make_float4(i1.x + o[4], i1.y + o[5], i1.z + o[6], i1.w + o[7]);
        float4* op = (float4*)(out + (size_t)e0 * D);
        op[0] = o0; op[1] = o1;
    }
    if (v1) {
        const float4* eap = (const float4*)(ea + (size_t)e1 * D);
        float4 i0 = eap[0], i1 = eap[1];
        float o[8];
#pragma unroll
        for (int d = 0; d < 8; d++) {
            float2 p = unpack2(accb[d]);
            o[d] = p.x + p.y + c8s[d];
        }
        float4 o0 = make_float4(i0.x + o[0], i0.y + o[1], i0.z + o[2], i0.w + o[3]);
        float4 o1 = make_float4(i1.x + o[4], i1.y + o[5], i1.z + o[6], i1.w + o[7]);
        float4* op = (float4*)(out + (size_t)e1 * D);
        op[0] = o0; op[1] = o1;
    }
}

// ---------------- launcher ----------------
extern "C" void kernel_launch(void* const* d_in, const int* in_sizes, int n_in,
                              void* d_out, int out_size) {
    const float* edge_attr     = (const float*)d_in[0];
    const float* node_features = (const float*)d_in[1];
    const int*   edge_index    = (const int*)  d_in[2];
    // d_in[3..8]: edge-encoder params — unused by the reference output
    const float* n_W1    = (const float*)d_in[9];
    const float* n_b1    = (const float*)d_in[10];
    const float* n_gamma = (const float*)d_in[11];
    const float* n_beta  = (const float*)d_in[12];
    const float* n_W2    = (const float*)d_in[13];
    const float* n_b2    = (const float*)d_in[14];
    const float* Wv      = (const float*)d_in[15];
    const float* bv      = (const float*)d_in[16];
    const float* Wo      = (const float*)d_in[17];
    const float* bo      = (const float*)d_in[18];
    const float* Wp      = (const float*)d_in[19];
    const float* bp      = (const float*)d_in[20];

    const int E = in_sizes[0] / D;
    float* out = (float*)d_out;

    k_fold1<<<16, 128>>>(Wo, Wp);
    k_fold2<<<16, 128>>>(Wv);
    k_fold3<<<16, 128>>>(n_W2, n_b2, bv, bo, bp, Wp);
    k_pass1<<<1184, 256>>>(node_features, edge_index, n_W1, n_b1, E);
    k_finalize<<<1, 256>>>(n_gamma, n_beta, 1.0f / (float)E);
    k_pass2<<<(E + 511) / 512, 256>>>(edge_attr, node_features, edge_index,
                                      n_W1, n_b1, out, E);
}

// round 4
// speedup vs baseline: 1.1741x; 1.0072x over previous
#include <cuda_runtime.h>

#define H 256
#define D 8
#define BN_EPS 1e-5f

typedef unsigned long long u64;

// ---------------- packed f32x2 helpers ----------------
__device__ __forceinline__ u64 ffma2(u64 a, u64 b, u64 c) {
    u64 d; asm("fma.rn.f32x2 %0, %1, %2, %3;" : "=l"(d) : "l"(a), "l"(b), "l"(c)); return d;
}
__device__ __forceinline__ u64 fadd2(u64 a, u64 b) {
    u64 d; asm("add.rn.f32x2 %0, %1, %2;" : "=l"(d) : "l"(a), "l"(b)); return d;
}
__device__ __forceinline__ u64 pack2(float lo, float hi) {
    u64 d; asm("mov.b64 %0, {%1, %2};" : "=l"(d) : "f"(lo), "f"(hi)); return d;
}
__device__ __forceinline__ float2 unpack2(u64 v) {
    float lo, hi; asm("mov.b64 {%0, %1}, %2;" : "=f"(lo), "=f"(hi) : "l"(v));
    return make_float2(lo, hi);
}
__device__ __forceinline__ u64 abs2(u64 v) {
    u64 d; asm("and.b64 %0, %1, 0x7FFFFFFF7FFFFFFF;" : "=l"(d) : "l"(v)); return d;
}
// relu2x: returns 2*relu per lane (q + |q|)
__device__ __forceinline__ u64 relu2x(u64 q) { return fadd2(q, abs2(q)); }

// ---------------- device scratch (static, allocation-free) ----------------
__device__ float g_P [H * D];   // Wo @ Wp
__device__ float g_T2[H * D];   // Wv @ P
__device__ float g_M [H * D];   // W2 @ T2
__device__ float g_c [D];       // folded bias chain
__device__ float g_sum  [H];    // per-column sum of r = 2h
__device__ float g_sumsq[H];    // per-column sum of r^2 = 4h^2
__device__ float g_Ms[H * D];   // 0.25 * diag(s) @ M
__device__ float g_c8[D];       // 0.5 * (t @ M + c)

// ---------------- fold kernels (tiny) ----------------
__global__ void k_fold1(const float* __restrict__ Wo, const float* __restrict__ Wp) {
    int t = blockIdx.x * blockDim.x + threadIdx.x;   // 0..2047
    int i = t >> 3, d = t & 7;
    float acc = 0.f;
#pragma unroll 8
    for (int k = 0; k < H; k++) acc = fmaf(Wo[i * H + k], Wp[k * D + d], acc);
    g_P[i * D + d] = acc;
    if (t < H) { g_sum[t] = 0.f; g_sumsq[t] = 0.f; }
}

__global__ void k_fold2(const float* __restrict__ Wv) {
    int t = blockIdx.x * blockDim.x + threadIdx.x;
    int i = t >> 3, d = t & 7;
    float acc = 0.f;
#pragma unroll 8
    for (int k = 0; k < H; k++) acc = fmaf(Wv[i * H + k], g_P[k * D + d], acc);
    g_T2[i * D + d] = acc;
}

__global__ void k_fold3(const float* __restrict__ W2, const float* __restrict__ b2,
                        const float* __restrict__ bv, const float* __restrict__ bo,
                        const float* __restrict__ bp, const float* __restrict__ Wp) {
    int t = blockIdx.x * blockDim.x + threadIdx.x;
    int i = t >> 3, d = t & 7;
    float acc = 0.f;
#pragma unroll 8
    for (int k = 0; k < H; k++) acc = fmaf(W2[i * H + k], g_T2[k * D + d], acc);
    g_M[i * D + d] = acc;
    if (t < D) {
        float c = bp[t];
        for (int k = 0; k < H; k++) {
            c = fmaf(b2[k], g_T2[k * D + t], c);
            c = fmaf(bv[k], g_P [k * D + t], c);
            c = fmaf(bo[k], Wp  [k * D + t], c);
        }
        g_c[t] = c;
    }
}

// ---------------- pass 1: batch statistics of h = relu(nc@W1 + b1) ----------------
// column-owner; 4 edges per iter (2 f32x2 packs, one LDS.128 per k).
__global__ void __launch_bounds__(256) k_pass1(
    const float* __restrict__ nf, const int* __restrict__ ei,
    const float* __restrict__ W1, const float* __restrict__ b1, int E) {
    __shared__ __align__(16) float ncsT[8][256];     // [k][edge-in-tile]
    const int t = threadIdx.x;

    u64 w2[8];
#pragma unroll
    for (int k = 0; k < 8; k++) { float w = W1[k * H + t]; w2[k] = pack2(w, w); }
    const float bb = b1[t];
    const u64 b2p = pack2(bb, bb);

    u64 sumA = pack2(0.f, 0.f), ssqA = sumA, sumB = sumA, ssqB = sumA;
    const int numTiles = (E + 255) >> 8;

    for (int tile = blockIdx.x; tile < numTiles; tile += gridDim.x) {
        const int base = tile << 8;
        const int cnt  = min(256, E - base);
        __syncthreads();                      // protect ncsT from prior readers
        if (t < cnt) {
            const int e  = base + t;
            const int s0 = ei[e];
            const int s1 = ei[E + e];
            const float4* a = (const float4*)(nf + (size_t)s0 * D);
            const float4* b = (const float4*)(nf + (size_t)s1 * D);
            float4 x0 = a[0], x1 = a[1], y0 = b[0], y1 = b[1];
            ncsT[0][t] = 0.5f * (x0.x + y0.x);
            ncsT[1][t] = 0.5f * (x0.y + y0.y);
            ncsT[2][t] = 0.5f * (x0.z + y0.z);
            ncsT[3][t] = 0.5f * (x0.w + y0.w);
            ncsT[4][t] = 0.5f * (x1.x + y1.x);
            ncsT[5][t] = 0.5f * (x1.y + y1.y);
            ncsT[6][t] = 0.5f * (x1.z + y1.z);
            ncsT[7][t] = 0.5f * (x1.w + y1.w);
        }
        __syncthreads();
        int e = 0;
        for (; e + 3 < cnt; e += 4) {          // 4 edges: one LDS.128 per k
            u64 q0 = b2p, q1 = b2p;
#pragma unroll
            for (int k = 0; k < 8; k++) {
                ulonglong2 n = *(const ulonglong2*)&ncsT[k][e];
                q0 = ffma2(n.x, w2[k], q0);
                q1 = ffma2(n.y, w2[k], q1);
            }
            u64 r0 = relu2x(q0);
            u64 r1 = relu2x(q1);
            sumA = fadd2(sumA, r0);      sumB = fadd2(sumB, r1);
            ssqA = ffma2(r0, r0, ssqA);  ssqB = ffma2(r1, r1, ssqB);
        }
        for (; e + 1 < cnt; e += 2) {
            u64 q0 = b2p;
#pragma unroll
            for (int k = 0; k < 8; k++)
                q0 = ffma2(*(const u64*)&ncsT[k][e], w2[k], q0);
            u64 r0 = relu2x(q0);
            sumA = fadd2(sumA, r0);
            ssqA = ffma2(r0, r0, ssqA);
        }
        if (e < cnt) {                        // odd tail: hi lane poisoned -> r=0
            u64 q0 = pack2(bb, -1e30f);
#pragma unroll
            for (int k = 0; k < 8; k++)
                q0 = ffma2(pack2(ncsT[k][e], 0.f), w2[k], q0);
            u64 r0 = relu2x(q0);
            sumA = fadd2(sumA, r0);
            ssqA = ffma2(r0, r0, ssqA);
        }
    }
    float2 sa = unpack2(fadd2(sumA, sumB));
    float2 qa = unpack2(fadd2(ssqA, ssqB));
    atomicAdd(&g_sum[t],   sa.x + sa.y);      // Σ r  (r = 2h)
    atomicAdd(&g_sumsq[t], qa.x + qa.y);      // Σ r²
}

// ---------------- finalize: fold BN affine (+relu-doubling factors) into M ----------------
__global__ void k_finalize(const float* __restrict__ gamma,
                           const float* __restrict__ beta, float invE) {
    __shared__ float tvs[H];
    const int j = threadIdx.x;
    float mu  = 0.5f  * g_sum[j]   * invE;              // E[h]
    float eh2 = 0.25f * g_sumsq[j] * invE;              // E[h^2]
    float var = fmaf(-mu, mu, eh2);                     // biased var
    float s   = gamma[j] * rsqrtf(var + BN_EPS);
    float tv  = fmaf(-mu, s, beta[j]);
#pragma unroll
    for (int d = 0; d < D; d++) g_Ms[j * D + d] = 0.25f * s * g_M[j * D + d];
    tvs[j] = tv;
    __syncthreads();
    if (j < D) {
        float acc = g_c[j];
        for (int k = 0; k < H; k++) acc = fmaf(tvs[k], g_M[k * D + j], acc);
        g_c8[j] = 0.5f * acc;
    }
}

// ---------------- pass 2: out = ea + (r @ Ms025) + c8h,  r = 2*relu(nc@W1+b1) ----------------
// edge-owner, 4 edges/thread, 128-thread blocks; cols packed in f32x2 lane pairs;
// weights/Ms read as LDS.128 (ulonglong2).
__global__ void __launch_bounds__(128) k_pass2(
    const float* __restrict__ ea, const float* __restrict__ nf,
    const int* __restrict__ ei,
    const float* __restrict__ W1, const float* __restrict__ b1,
    float* __restrict__ out, int E) {
    __shared__ __align__(16) u64 w2p [128 * 8];   // [jp][k]  = (W1[k][2jp], W1[k][2jp+1])
    __shared__ __align__(16) u64 ms2p[128 * 8];   // [jp][d]  = (Ms[2jp][d], Ms[2jp+1][d])
    __shared__ u64 b2ps[128];                     // (b1[2jp], b1[2jp+1])
    __shared__ float c8s[D];

    const int t = threadIdx.x;
    for (int idx = t; idx < 128 * 8; idx += 128) {
        int jp = idx >> 3, k = idx & 7;
        w2p [idx] = pack2(W1[k * H + 2 * jp], W1[k * H + 2 * jp + 1]);
        ms2p[idx] = pack2(g_Ms[(2 * jp) * D + k], g_Ms[(2 * jp + 1) * D + k]);
    }
    b2ps[t] = pack2(b1[2 * t], b1[2 * t + 1]);
    if (t < D) c8s[t] = g_c8[t];
    __syncthreads();

    int eidx[4]; bool val[4];
#pragma unroll
    for (int i = 0; i < 4; i++) {
        int er = blockIdx.x * 512 + i * 128 + t;
        val[i]  = er < E;
        eidx[i] = val[i] ? er : E - 1;
    }

    // gather + duplicate-pack nc for 4 edges
    u64 nc[4][8];
#pragma unroll
    for (int i = 0; i < 4; i++) {
        const int s0 = ei[eidx[i]];
        const int s1 = ei[E + eidx[i]];
        const float4* p0 = (const float4*)(nf + (size_t)s0 * D);
        const float4* p1 = (const float4*)(nf + (size_t)s1 * D);
        float4 x0 = p0[0], x1 = p0[1], y0 = p1[0], y1 = p1[1];
        float n[8];
        n[0] = 0.5f * (x0.x + y0.x); n[1] = 0.5f * (x0.y + y0.y);
        n[2] = 0.5f * (x0.z + y0.z); n[3] = 0.5f * (x0.w + y0.w);
        n[4] = 0.5f * (x1.x + y1.x); n[5] = 0.5f * (x1.y + y1.y);
        n[6] = 0.5f * (x1.z + y1.z); n[7] = 0.5f * (x1.w + y1.w);
#pragma unroll
        for (int k = 0; k < 8; k++) nc[i][k] = pack2(n[k], n[k]);
    }

    u64 acc[4][8];
    const u64 z = pack2(0.f, 0.f);
#pragma unroll
    for (int i = 0; i < 4; i++)
#pragma unroll
        for (int d = 0; d < 8; d++) acc[i][d] = z;

#pragma unroll 1
    for (int jp = 0; jp < 128; jp++) {
        ulonglong2 wv0 = *(const ulonglong2*)&w2p[jp * 8 + 0];
        ulonglong2 wv1 = *(const ulonglong2*)&w2p[jp * 8 + 2];
        ulonglong2 wv2 = *(const ulonglong2*)&w2p[jp * 8 + 4];
        ulonglong2 wv3 = *(const ulonglong2*)&w2p[jp * 8 + 6];
        const u64 bp = b2ps[jp];
        u64 q0 = bp, q1 = bp, q2 = bp, q3 = bp;
        q0 = ffma2(nc[0][0], wv0.x, q0); q1 = ffma2(nc[1][0], wv0.x, q1);
        q2 = ffma2(nc[2][0], wv0.x, q2); q3 = ffma2(nc[3][0], wv0.x, q3);
        q0 = ffma2(nc[0][1], wv0.y, q0); q1 = ffma2(nc[1][1], wv0.y, q1);
        q2 = ffma2(nc[2][1], wv0.y, q2); q3 = ffma2(nc[3][1], wv0.y, q3);
        q0 = ffma2(nc[0][2], wv1.x, q0); q1 = ffma2(nc[1][2], wv1.x, q1);
        q2 = ffma2(nc[2][2], wv1.x, q2); q3 = ffma2(nc[3][2], wv1.x, q3);
        q0 = ffma2(nc[0][3], wv1.y, q0); q1 = ffma2(nc[1][3], wv1.y, q1);
        q2 = ffma2(nc[2][3], wv1.y, q2); q3 = ffma2(nc[3][3], wv1.y, q3);
        q0 = ffma2(nc[0][4], wv2.x, q0); q1 = ffma2(nc[1][4], wv2.x, q1);
        q2 = ffma2(nc[2][4], wv2.x, q2); q3 = ffma2(nc[3][4], wv2.x, q3);
        q0 = ffma2(nc[0][5], wv2.y, q0); q1 = ffma2(nc[1][5], wv2.y, q1);
        q2 = ffma2(nc[2][5], wv2.y, q2); q3 = ffma2(nc[3][5], wv2.y, q3);
        q0 = ffma2(nc[0][6], wv3.x, q0); q1 = ffma2(nc[1][6], wv3.x, q1);
        q2 = ffma2(nc[2][6], wv3.x, q2); q3 = ffma2(nc[3][6], wv3.x, q3);
        q0 = ffma2(nc[0][7], wv3.y, q0); q1 = ffma2(nc[1][7], wv3.y, q1);
        q2 = ffma2(nc[2][7], wv3.y, q2); q3 = ffma2(nc[3][7], wv3.y, q3);

        u64 r0 = relu2x(q0), r1 = relu2x(q1), r2 = relu2x(q2), r3 = relu2x(q3);

        ulonglong2 mv0 = *(const ulonglong2*)&ms2p[jp * 8 + 0];
        ulonglong2 mv1 = *(const ulonglong2*)&ms2p[jp * 8 + 2];
        ulonglong2 mv2 = *(const ulonglong2*)&ms2p[jp * 8 + 4];
        ulonglong2 mv3 = *(const ulonglong2*)&ms2p[jp * 8 + 6];
        acc[0][0] = ffma2(r0, mv0.x, acc[0][0]); acc[1][0] = ffma2(r1, mv0.x, acc[1][0]);
        acc[2][0] = ffma2(r2, mv0.x, acc[2][0]); acc[3][0] = ffma2(r3, mv0.x, acc[3][0]);
        acc[0][1] = ffma2(r0, mv0.y, acc[0][1]); acc[1][1] = ffma2(r1, mv0.y, acc[1][1]);
        acc[2][1] = ffma2(r2, mv0.y, acc[2][1]); acc[3][1] = ffma2(r3, mv0.y, acc[3][1]);
        acc[0][2] = ffma2(r0, mv1.x, acc[0][2]); acc[1][2] = ffma2(r1, mv1.x, acc[1][2]);
        acc[2][2] = ffma2(r2, mv1.x, acc[2][2]); acc[3][2] = ffma2(r3, mv1.x, acc[3][2]);
        acc[0][3] = ffma2(r0, mv1.y, acc[0][3]); acc[1][3] = ffma2(r1, mv1.y, acc[1][3]);
        acc[2][3] = ffma2(r2, mv1.y, acc[2][3]); acc[3][3] = ffma2(r3, mv1.y, acc[3][3]);
        acc[0][4] = ffma2(r0, mv2.x, acc[0][4]); acc[1][4] = ffma2(r1, mv2.x, acc[1][4]);
        acc[2][4] = ffma2(r2, mv2.x, acc[2][4]); acc[3][4] = ffma2(r3, mv2.x, acc[3][4]);
        acc[0][5] = ffma2(r0, mv2.y, acc[0][5]); acc[1][5] = ffma2(r1, mv2.y, acc[1][5]);
        acc[2][5] = ffma2(r2, mv2.y, acc[2][5]); acc[3][5] = ffma2(r3, mv2.y, acc[3][5]);
        acc[0][6] = ffma2(r0, mv3.x, acc[0][6]); acc[1][6] = ffma2(r1, mv3.x, acc[1][6]);
        acc[2][6] = ffma2(r2, mv3.x, acc[2][6]); acc[3][6] = ffma2(r3, mv3.x, acc[3][6]);
        acc[0][7] = ffma2(r0, mv3.y, acc[0][7]); acc[1][7] = ffma2(r1, mv3.y, acc[1][7]);
        acc[2][7] = ffma2(r2, mv3.y, acc[2][7]); acc[3][7] = ffma2(r3, mv3.y, acc[3][7]);
    }

#pragma unroll
    for (int i = 0; i < 4; i++) {
        if (!val[i]) continue;
        const float4* eap = (const float4*)(ea + (size_t)eidx[i] * D);
        float4 i0 = eap[0], i1 = eap[1];
        float o[8];
#pragma unroll
        for (int d = 0; d < 8; d++) {
            float2 p = unpack2(acc[i][d]);
            o[d] = p.x + p.y + c8s[d];
        }
        float4 o0 = make_float4(i0.x + o[0], i0.y + o[1], i0.z + o[2], i0.w + o[3]);
        float4 o1 = make_float4(i1.x + o[4], i1.y + o[5], i1.z + o[6], i1.w + o[7]);
        float4* op = (float4*)(out + (size_t)eidx[i] * D);
        op[0] = o0; op[1] = o1;
    }
}

// ---------------- launcher ----------------
extern "C" void kernel_launch(void* const* d_in, const int* in_sizes, int n_in,
                              void* d_out, int out_size) {
    const float* edge_attr     = (const float*)d_in[0];
    const float* node_features = (const float*)d_in[1];
    const int*   edge_index    = (const int*)  d_in[2];
    // d_in[3..8]: edge-encoder params — unused by the reference output
    const float* n_W1    = (const float*)d_in[9];
    const float* n_b1    = (const float*)d_in[10];
    const float* n_gamma = (const float*)d_in[11];
    const float* n_beta  = (const float*)d_in[12];
    const float* n_W2    = (const float*)d_in[13];
    const float* n_b2    = (const float*)d_in[14];
    const float* Wv      = (const float*)d_in[15];
    const float* bv      = (const float*)d_in[16];
    const float* Wo      = (const float*)d_in[17];
    const float* bo      = (const float*)d_in[18];
    const float* Wp      = (const float*)d_in[19];
    const float* bp      = (const float*)d_in[20];

    const int E = in_sizes[0] / D;
    float* out = (float*)d_out;

    k_fold1<<<16, 128>>>(Wo, Wp);
    k_fold2<<<16, 128>>>(Wv);
    k_fold3<<<16, 128>>>(n_W2, n_b2, bv, bo, bp, Wp);
    k_pass1<<<1184, 256>>>(node_features, edge_index, n_W1, n_b1, E);
    k_finalize<<<1, 256>>>(n_gamma, n_beta, 1.0f / (float)E);
    k_pass2<<<(E + 511) / 512, 128>>>(edge_attr, node_features, edge_index,
                                      n_W1, n_b1, out, E);
}